// round 8
// baseline (speedup 1.0000x reference)
#include <cuda_runtime.h>
#include <cuda_bf16.h>

// D_MODEL = 2048, QUAT_DIM = 512, B*T = 16384
// Inputs: x [B,T,2048] f32, q_left [4,512] f32, q_right [4,512] f32, gate [512] f32
// Output: [B,T,2048] f32
//
// gate broadcasts uniformly over the FFT axis => ifft(fft(x)*g).real == g*x.
// Both Hamilton products are linear in x => fused per-feature 4x4 matrix M[d].
//
// R6: float2-per-thread (256 thr/blk) + 2-row software prefetch pipeline to
// triple in-flight load bytes per SM (MLP-limited at 5.2 TB/s previously).

#define QD 512
#define NBT (4 * 4096)
#define ROWS 8
#define NBLK (NBT / ROWS)    // 2048
#define THREADS 256

__device__ __forceinline__ float2 f2_fma(float2 a, float2 b, float2 c) {
    return make_float2(fmaf(a.x, b.x, c.x), fmaf(a.y, b.y, c.y));
}
__device__ __forceinline__ float2 f2_mul(float2 a, float2 b) {
    return make_float2(a.x * b.x, a.y * b.y);
}

__global__ void __launch_bounds__(THREADS)
evolve_f2_kernel(const float* __restrict__ x,
                 const float* __restrict__ ql,
                 const float* __restrict__ qr,
                 const float* __restrict__ gate,
                 float* __restrict__ out) {
    const int d2 = threadIdx.x * 2;       // feature pair (multiple of 2)
    const int bt0 = blockIdx.x * ROWS;

    // ---- Build fused 4x4 matrices for 2 features (elementwise float2) ----
    float2 lv[4], rv[4];
#pragma unroll
    for (int i = 0; i < 4; i++) {
        lv[i] = *reinterpret_cast<const float2*>(ql + i * QD + d2);
        rv[i] = *reinterpret_cast<const float2*>(qr + i * QD + d2);
    }
    {   // normalize l
        float2 s = make_float2(1e-8f, 1e-8f);
#pragma unroll
        for (int i = 0; i < 4; i++) s = f2_fma(lv[i], lv[i], s);
        float2 inv = make_float2(rsqrtf(s.x), rsqrtf(s.y));
#pragma unroll
        for (int i = 0; i < 4; i++) lv[i] = f2_mul(lv[i], inv);
    }
    {   // normalize r + conjugate
        float2 s = make_float2(1e-8f, 1e-8f);
#pragma unroll
        for (int i = 0; i < 4; i++) s = f2_fma(rv[i], rv[i], s);
        float2 inv = make_float2(rsqrtf(s.x), rsqrtf(s.y));
        rv[0] = f2_mul(rv[0], inv);
        float2 ninv = make_float2(-inv.x, -inv.y);
#pragma unroll
        for (int i = 1; i < 4; i++) rv[i] = f2_mul(rv[i], ninv);
    }

    // Hamilton structure tables (constant-folded under full unroll):
    // L[r][k] = sL[r][k]*l[p[r][k]],  R[k][c] = sR[k][c]*r[p[k][c]]
    const int   pP[4][4] = {{0,1,2,3},{1,0,3,2},{2,3,0,1},{3,2,1,0}};
    const float sL[4][4] = {{1,-1,-1,-1},{1,1,-1,1},{1,1,1,-1},{1,-1,1,1}};
    const float sR[4][4] = {{1,-1,-1,-1},{1,1,1,-1},{1,-1,1,1},{1,1,-1,1}};

    float2 g2 = *reinterpret_cast<const float2*>(gate + d2);

    float2 M[16];
#pragma unroll
    for (int r = 0; r < 4; r++) {
#pragma unroll
        for (int c = 0; c < 4; c++) {
            float2 acc = make_float2(0.f, 0.f);
#pragma unroll
            for (int k = 0; k < 4; k++) {
                float2 t = f2_mul(lv[pP[r][k]], rv[pP[k][c]]);
                if (sL[r][k] * sR[k][c] > 0.f) {
                    acc.x += t.x; acc.y += t.y;
                } else {
                    acc.x -= t.x; acc.y -= t.y;
                }
            }
            M[r * 4 + c] = f2_mul(acc, g2);
        }
    }

    // ---- Stream ROWS rows with a 2-deep software prefetch pipeline ----
    const float* xp = x + (size_t)bt0 * 2048 + d2;
    float* op = out + (size_t)bt0 * 2048 + d2;

    float2 buf[2][4];
#pragma unroll
    for (int c = 0; c < 4; c++) {
        buf[0][c] = __ldcs(reinterpret_cast<const float2*>(xp + 0 * 2048 + c * QD));
        buf[1][c] = __ldcs(reinterpret_cast<const float2*>(xp + 1 * 2048 + c * QD));
    }

#pragma unroll
    for (int rr = 0; rr < ROWS; rr++) {
        float2 in[4];
#pragma unroll
        for (int c = 0; c < 4; c++) in[c] = buf[rr & 1][c];

        if (rr + 2 < ROWS) {
#pragma unroll
            for (int c = 0; c < 4; c++)
                buf[rr & 1][c] = __ldcs(reinterpret_cast<const float2*>(
                    xp + (size_t)(rr + 2) * 2048 + c * QD));
        }

#pragma unroll
        for (int r = 0; r < 4; r++) {
            float2 a = f2_mul(M[r * 4 + 0], in[0]);
            a = f2_fma(M[r * 4 + 1], in[1], a);
            a = f2_fma(M[r * 4 + 2], in[2], a);
            a = f2_fma(M[r * 4 + 3], in[3], a);
            __stcs(reinterpret_cast<float2*>(op + (size_t)rr * 2048 + r * QD), a);
        }
    }
}

extern "C" void kernel_launch(void* const* d_in, const int* in_sizes, int n_in,
                              void* d_out, int out_size) {
    const float* x    = (const float*)d_in[0];
    const float* ql   = (const float*)d_in[1];
    const float* qr   = (const float*)d_in[2];
    const float* gate = (const float*)d_in[3];
    float* out = (float*)d_out;

    evolve_f2_kernel<<<NBLK, THREADS>>>(x, ql, qr, gate, out);
}